// round 13
// baseline (speedup 1.0000x reference)
#include <cuda_runtime.h>
#include <cuda_bf16.h>

// Problem constants (fixed by the dataset)
#define BB   4
#define HH   8
#define NN   256
#define DVD  64
#define NKD  64
#define EKD  16
#define QD   80      // NK_DIM + EK_DIM
#define TQ   16      // queries per block
#define KC   64      // nk keys per smem chunk
#define NKPAD 68     // padded row stride (floats) for conflict-free LDS

// ---- packed fp32x2 helpers (FFMA2; ptxas never emits these from C++) ----
__device__ __forceinline__ unsigned long long ffma2(unsigned long long a,
                                                    unsigned long long b,
                                                    unsigned long long c) {
    unsigned long long d;
    asm("fma.rn.f32x2 %0, %1, %2, %3;" : "=l"(d) : "l"(a), "l"(b), "l"(c));
    return d;
}
__device__ __forceinline__ unsigned long long pack2(float lo, float hi) {
    unsigned long long r;
    asm("mov.b64 %0, {%1, %2};" : "=l"(r) : "f"(lo), "f"(hi));
    return r;
}
__device__ __forceinline__ float hadd2(unsigned long long a) {
    float lo, hi;
    asm("mov.b64 {%0, %1}, %2;" : "=f"(lo), "=f"(hi) : "l"(a));
    return lo + hi;
}

// ============================================================
// Fused kernel: edge pass (coalesced + shfl-reduce) -> node
// chunks -> softmax -> attn + P@V.
// grid = 32 (b*h) * 16 (q tiles) = 512 blocks, 256 threads.
// ============================================================
__global__ __launch_bounds__(256, 5)
void sdpea_kernel(const float* __restrict__ qg,
                  const float* __restrict__ nk,
                  const float* __restrict__ ek,
                  const float* __restrict__ v,
                  const int*   __restrict__ mask,
                  float* __restrict__ out,       // [B,H,N,DV]
                  float* __restrict__ attn_out)  // [B,H,N,N]
{
    __shared__ float qsm[TQ][QD];      // q tile (qn||qe), rows 320B (16B aligned)
    __shared__ float Ssm[TQ][NN];      // edge scores -> full scores -> probs
    __shared__ float nks[KC][NKPAD];   // nk chunk, padded

    const int bx = blockIdx.x;
    const int bh = bx >> 4;          // 0..31  (b*H + h)
    const int qt = bx & 15;          // 0..15
    const int b  = bh >> 3;
    const int q0 = qt * TQ;
    const int t  = threadIdx.x;      // 0..255

    // ---- load q tile (16 x 80 floats) ----
    for (int i = t; i < TQ * QD; i += 256) {
        int qq = i / QD, d = i % QD;
        qsm[qq][d] = qg[(size_t)((bh * NN) + q0 + qq) * QD + d];
    }
    __syncthreads();

    const float* ekb = ek + (size_t)bh * NN * NN * EKD;   // [q][k][16]

    // ---- phase E: edge scores -> Ssm (raw, unscaled) ----
    // warp covers 8 contiguous rows/iter; lane = (kk = row-in-8, ii = 16B seg).
    // Warp LDG footprint = 512B contiguous = 4 wavefronts (fully coalesced).
    {
        const int w    = t >> 5;
        const int lane = t & 31;
        const int kk   = lane >> 2;
        const int ii   = lane & 3;
        #pragma unroll 8
        for (int it = 0; it < 64; it++) {
            const int r    = it * 64 + w * 8 + kk;   // 0..4095
            const int ql   = r >> 8;                 // local q (0..15)
            const int kidx = r & 255;                // key (0..255)
            const float4 e = *(const float4*)
                (ekb + ((size_t)(q0 + ql) * NN + kidx) * EKD + ii * 4);
            const float4 qe = *(const float4*)&qsm[ql][NKD + ii * 4];
            float s = e.x * qe.x + e.y * qe.y + e.z * qe.z + e.w * qe.w;
            s += __shfl_xor_sync(0xffffffffu, s, 1);
            s += __shfl_xor_sync(0xffffffffu, s, 2);
            if (ii == 0) Ssm[ql][kidx] = s;
        }
    }

    // ---- phase N: node scores in 4 key-chunks of 64, += edge ----
    // thread = (k_local = t&63, q_group g = t>>6); queries {g, g+4, g+8, g+12}
    const int kl = t & 63;
    const int g  = t >> 6;
    const int* mb = mask + (size_t)b * NN * NN;

    for (int c = 0; c < 4; c++) {
        const int kbase = c * KC;
        __syncthreads();   // phase-E writes (c==0) / prev chunk readers (c>0)

        // coalesced stage: 64 rows x 64 floats, 4 float4 per thread
        {
            const float4* src = (const float4*)(nk + (size_t)(bh * NN + kbase) * NKD);
            #pragma unroll
            for (int it = 0; it < 4; it++) {
                const int idx  = t + it * 256;       // 0..1023
                const int row  = idx >> 4;           // /16
                const int col4 = idx & 15;
                const float4 vv = src[(size_t)row * 16 + col4];
                *(float4*)&nks[row][col4 * 4] = vv;
            }
        }
        __syncthreads();

        const int k = kbase + kl;

        // prefetch edge scores + mask for this thread's 4 (q,k) pairs
        float ev[4]; int m[4];
        #pragma unroll
        for (int j = 0; j < 4; j++) {
            ev[j] = Ssm[g + 4 * j][k];
            m[j]  = mb[(q0 + g + 4 * j) * NN + k];
        }

        // packed dot products: acc[q] is an f32x2 pair, halves summed at end
        unsigned long long a0 = 0ull, a1 = 0ull, a2 = 0ull, a3 = 0ull;
        #pragma unroll
        for (int i = 0; i < 16; i++) {
            const ulonglong2 nv  = *(const ulonglong2*)&nks[kl][4 * i];
            const ulonglong2 q0v = *(const ulonglong2*)&qsm[g     ][4 * i];
            const ulonglong2 q1v = *(const ulonglong2*)&qsm[g +  4][4 * i];
            const ulonglong2 q2v = *(const ulonglong2*)&qsm[g +  8][4 * i];
            const ulonglong2 q3v = *(const ulonglong2*)&qsm[g + 12][4 * i];
            a0 = ffma2(nv.x, q0v.x, a0); a0 = ffma2(nv.y, q0v.y, a0);
            a1 = ffma2(nv.x, q1v.x, a1); a1 = ffma2(nv.y, q1v.y, a1);
            a2 = ffma2(nv.x, q2v.x, a2); a2 = ffma2(nv.y, q2v.y, a2);
            a3 = ffma2(nv.x, q3v.x, a3); a3 = ffma2(nv.y, q3v.y, a3);
        }

        float sv;
        sv = (hadd2(a0) + ev[0]) * 0.125f; if (m[0] == 0) sv = -1000000000.0f; Ssm[g     ][k] = sv;
        sv = (hadd2(a1) + ev[1]) * 0.125f; if (m[1] == 0) sv = -1000000000.0f; Ssm[g +  4][k] = sv;
        sv = (hadd2(a2) + ev[2]) * 0.125f; if (m[2] == 0) sv = -1000000000.0f; Ssm[g +  8][k] = sv;
        sv = (hadd2(a3) + ev[3]) * 0.125f; if (m[3] == 0) sv = -1000000000.0f; Ssm[g + 12][k] = sv;
    }
    __syncthreads();

    // ---- phase 2: softmax, one warp per row (8 warps, 16 rows) ----
    {
        const int w = t >> 5, lane = t & 31;
        for (int qq = w; qq < TQ; qq += 8) {
            float vals[8];
            float mx = -3.4e38f;
            #pragma unroll
            for (int i = 0; i < 8; i++) {
                vals[i] = Ssm[qq][lane + 32 * i];
                mx = fmaxf(mx, vals[i]);
            }
            #pragma unroll
            for (int o = 16; o > 0; o >>= 1)
                mx = fmaxf(mx, __shfl_xor_sync(0xffffffffu, mx, o));
            float sum = 0.f;
            #pragma unroll
            for (int i = 0; i < 8; i++) {
                vals[i] = __expf(vals[i] - mx);
                sum += vals[i];
            }
            #pragma unroll
            for (int o = 16; o > 0; o >>= 1)
                sum += __shfl_xor_sync(0xffffffffu, sum, o);
            const float inv = 1.f / sum;
            float* arow = attn_out + (size_t)((bh * NN) + q0 + qq) * NN;
            #pragma unroll
            for (int i = 0; i < 8; i++) {
                float p = vals[i] * inv;
                Ssm[qq][lane + 32 * i] = p;
                arow[lane + 32 * i]    = p;
            }
        }
    }
    __syncthreads();

    // ---- phase 3: output = P @ V ; thread owns (d, 4 q-rows) ----
    // k unrolled by 4: uniform LDS.128 probs (pre-packed pairs) + packed FMAs.
    {
        const int d = t & 63, gg = t >> 6;      // gg in 0..3
        unsigned long long acc0 = 0ull, acc1 = 0ull, acc2 = 0ull, acc3 = 0ull;
        const float* vb = v + (size_t)bh * NN * DVD + d;
        #pragma unroll 4
        for (int k = 0; k < NN; k += 4) {
            const float v0 = vb[(size_t)(k    ) * DVD];
            const float v1 = vb[(size_t)(k + 1) * DVD];
            const float v2 = vb[(size_t)(k + 2) * DVD];
            const float v3 = vb[(size_t)(k + 3) * DVD];
            const unsigned long long vp01 = pack2(v0, v1);
            const unsigned long long vp23 = pack2(v2, v3);
            const ulonglong2 p0 = *(const ulonglong2*)&Ssm[gg     ][k];
            const ulonglong2 p1 = *(const ulonglong2*)&Ssm[gg +  4][k];
            const ulonglong2 p2 = *(const ulonglong2*)&Ssm[gg +  8][k];
            const ulonglong2 p3 = *(const ulonglong2*)&Ssm[gg + 12][k];
            acc0 = ffma2(p0.x, vp01, acc0); acc0 = ffma2(p0.y, vp23, acc0);
            acc1 = ffma2(p1.x, vp01, acc1); acc1 = ffma2(p1.y, vp23, acc1);
            acc2 = ffma2(p2.x, vp01, acc2); acc2 = ffma2(p2.y, vp23, acc2);
            acc3 = ffma2(p3.x, vp01, acc3); acc3 = ffma2(p3.y, vp23, acc3);
        }
        float* ob = out + (size_t)((bh * NN) + q0) * DVD + d;
        ob[(size_t)(gg     ) * DVD] = hadd2(acc0);
        ob[(size_t)(gg +  4) * DVD] = hadd2(acc1);
        ob[(size_t)(gg +  8) * DVD] = hadd2(acc2);
        ob[(size_t)(gg + 12) * DVD] = hadd2(acc3);
    }
}

extern "C" void kernel_launch(void* const* d_in, const int* in_sizes, int n_in,
                              void* d_out, int out_size)
{
    const float* q    = (const float*)d_in[0];
    const float* nk   = (const float*)d_in[1];
    const float* ek   = (const float*)d_in[2];
    const float* v    = (const float*)d_in[3];
    const int*   mask = (const int*)d_in[4];

    float* out      = (float*)d_out;                       // [4,8,256,64]
    float* attn_out = out + (size_t)BB * HH * NN * DVD;    // [4,8,256,256]

    sdpea_kernel<<<BB * HH * (NN / TQ), 256>>>(q, nk, ek, v, mask,
                                               out, attn_out);
}

// round 14
// speedup vs baseline: 1.2750x; 1.2750x over previous
#include <cuda_runtime.h>
#include <cuda_bf16.h>

// Problem constants (fixed by the dataset)
#define BB   4
#define HH   8
#define NN   256
#define DVD  64
#define NKD  64
#define EKD  16
#define QD   80      // NK_DIM + EK_DIM
#define TQ   16      // queries per block
#define KC   64      // nk keys per smem chunk
#define NKPAD 68     // padded row stride (floats) for conflict-free nk LDS
#define EKROW 20     // padded row stride (floats) for conflict-free ek LDS

// ---- packed fp32x2 helpers (FFMA2; ptxas never emits these from C++) ----
__device__ __forceinline__ unsigned long long ffma2(unsigned long long a,
                                                    unsigned long long b,
                                                    unsigned long long c) {
    unsigned long long d;
    asm("fma.rn.f32x2 %0, %1, %2, %3;" : "=l"(d) : "l"(a), "l"(b), "l"(c));
    return d;
}
__device__ __forceinline__ unsigned long long pack2(float lo, float hi) {
    unsigned long long r;
    asm("mov.b64 %0, {%1, %2};" : "=l"(r) : "f"(lo), "f"(hi));
    return r;
}
__device__ __forceinline__ float hadd2(unsigned long long a) {
    float lo, hi;
    asm("mov.b64 {%0, %1}, %2;" : "=f"(lo), "=f"(hi) : "l"(a));
    return lo + hi;
}

// ============================================================
// Fused kernel: per key-chunk { ek smem-staged edge dots (4
// sub-rounds, coalesced) -> nk smem-staged node dots (same
// buffer reused) } -> softmax -> attn + P@V.
// grid = 32 (b*h) * 16 (q tiles) = 512 blocks, 256 threads.
// ============================================================
__global__ __launch_bounds__(256, 5)
void sdpea_kernel(const float* __restrict__ qg,
                  const float* __restrict__ nk,
                  const float* __restrict__ ek,
                  const float* __restrict__ v,
                  const int*   __restrict__ mask,
                  float* __restrict__ out,       // [B,H,N,DV]
                  float* __restrict__ attn_out)  // [B,H,N,N]
{
    __shared__ __align__(16) float qsm[TQ][QD];   // q tile (qn||qe)
    __shared__ __align__(16) float Ssm[TQ][NN];   // scores -> probs
    // union buffer: ek stage (4 q x 64 k x EKROW = 5120 floats) OR
    //               nk chunk (64 x NKPAD = 4352 floats)
    __shared__ __align__(16) float ubuf[4 * KC * EKROW];

    const int bx = blockIdx.x;
    const int bh = bx >> 4;          // 0..31  (b*H + h)
    const int qt = bx & 15;          // 0..15
    const int b  = bh >> 3;
    const int q0 = qt * TQ;
    const int t  = threadIdx.x;      // 0..255

    // ---- load q tile (16 x 80 floats) ----
    for (int i = t; i < TQ * QD; i += 256) {
        int qq = i / QD, d = i % QD;
        qsm[qq][d] = qg[(size_t)((bh * NN) + q0 + qq) * QD + d];
    }

    // ---- phase 1: scores in 4 key-chunks of 64 ----
    // thread = (k_local = t&63, q_group g = t>>6); queries {g, g+4, g+8, g+12}
    const int kl = t & 63;
    const int g  = t >> 6;
    const int*   mb  = mask + (size_t)b * NN * NN;
    const float* ekb = ek + (size_t)bh * NN * NN * EKD;   // [q][k][16]

    for (int c = 0; c < 4; c++) {
        const int kbase = c * KC;
        const int k     = kbase + kl;
        float eacc[4];

        // ---- edge part: 4 sub-rounds of 4 queries each ----
        // sub-round jj stages ek[q0+4jj+0..3][kbase..kbase+63][:] (16 KB)
        // coalesced, then group g consumes query ql = 4*jj + g.
        #pragma unroll
        for (int jj = 0; jj < 4; jj++) {
            __syncthreads();   // previous ubuf content fully consumed
            #pragma unroll
            for (int it = 0; it < 4; it++) {
                const int idx = it * 256 + t;        // 0..1023 float4 slots
                const int q4  = idx >> 8;
                const int kk  = (idx >> 2) & 63;
                const int seg = idx & 3;
                const float4 e = *(const float4*)
                    (ekb + ((size_t)(q0 + 4 * jj + q4) * NN + kbase + kk) * EKD
                         + seg * 4);
                *(float4*)&ubuf[(q4 * KC + kk) * EKROW + seg * 4] = e;
            }
            __syncthreads();

            // conflict-free row read (80B stride), FFMA2 dot vs broadcast qe
            const ulonglong2* er =
                (const ulonglong2*)&ubuf[(g * KC + kl) * EKROW];
            const ulonglong2* qe =
                (const ulonglong2*)&qsm[4 * jj + g][NKD];
            unsigned long long a = 0ull;
            const ulonglong2 e0 = er[0], e1 = er[1], e2 = er[2], e3 = er[3];
            a = ffma2(e0.x, qe[0].x, a); a = ffma2(e0.y, qe[0].y, a);
            a = ffma2(e1.x, qe[1].x, a); a = ffma2(e1.y, qe[1].y, a);
            a = ffma2(e2.x, qe[2].x, a); a = ffma2(e2.y, qe[2].y, a);
            a = ffma2(e3.x, qe[3].x, a); a = ffma2(e3.y, qe[3].y, a);
            eacc[jj] = hadd2(a);
        }

        // ---- node part: stage nk chunk into the SAME buffer ----
        __syncthreads();   // edge reads of ubuf done
        {
            const float4* src = (const float4*)(nk + (size_t)(bh * NN + kbase) * NKD);
            #pragma unroll
            for (int it = 0; it < 4; it++) {
                const int idx  = t + it * 256;       // 0..1023
                const int row  = idx >> 4;           // /16
                const int col4 = idx & 15;
                const float4 vv = src[(size_t)row * 16 + col4];
                *(float4*)&ubuf[row * NKPAD + col4 * 4] = vv;
            }
        }
        __syncthreads();

        // mask prefetch for this thread's 4 (q,k) pairs
        int m[4];
        #pragma unroll
        for (int j = 0; j < 4; j++)
            m[j] = mb[(q0 + g + 4 * j) * NN + k];

        // packed dot products: acc[q] is an f32x2 pair, halves summed at end
        unsigned long long a0 = 0ull, a1 = 0ull, a2 = 0ull, a3 = 0ull;
        #pragma unroll
        for (int i = 0; i < 16; i++) {
            const ulonglong2 nv  = *(const ulonglong2*)&ubuf[kl * NKPAD + 4 * i];
            const ulonglong2 q0v = *(const ulonglong2*)&qsm[g     ][4 * i];
            const ulonglong2 q1v = *(const ulonglong2*)&qsm[g +  4][4 * i];
            const ulonglong2 q2v = *(const ulonglong2*)&qsm[g +  8][4 * i];
            const ulonglong2 q3v = *(const ulonglong2*)&qsm[g + 12][4 * i];
            a0 = ffma2(nv.x, q0v.x, a0); a0 = ffma2(nv.y, q0v.y, a0);
            a1 = ffma2(nv.x, q1v.x, a1); a1 = ffma2(nv.y, q1v.y, a1);
            a2 = ffma2(nv.x, q2v.x, a2); a2 = ffma2(nv.y, q2v.y, a2);
            a3 = ffma2(nv.x, q3v.x, a3); a3 = ffma2(nv.y, q3v.y, a3);
        }

        float sv;
        sv = (hadd2(a0) + eacc[0]) * 0.125f; if (m[0] == 0) sv = -1000000000.0f; Ssm[g     ][k] = sv;
        sv = (hadd2(a1) + eacc[1]) * 0.125f; if (m[1] == 0) sv = -1000000000.0f; Ssm[g +  4][k] = sv;
        sv = (hadd2(a2) + eacc[2]) * 0.125f; if (m[2] == 0) sv = -1000000000.0f; Ssm[g +  8][k] = sv;
        sv = (hadd2(a3) + eacc[3]) * 0.125f; if (m[3] == 0) sv = -1000000000.0f; Ssm[g + 12][k] = sv;
    }
    __syncthreads();

    // ---- phase 2: softmax, one warp per row (8 warps, 16 rows) ----
    {
        const int w = t >> 5, lane = t & 31;
        for (int qq = w; qq < TQ; qq += 8) {
            float vals[8];
            float mx = -3.4e38f;
            #pragma unroll
            for (int i = 0; i < 8; i++) {
                vals[i] = Ssm[qq][lane + 32 * i];
                mx = fmaxf(mx, vals[i]);
            }
            #pragma unroll
            for (int o = 16; o > 0; o >>= 1)
                mx = fmaxf(mx, __shfl_xor_sync(0xffffffffu, mx, o));
            float sum = 0.f;
            #pragma unroll
            for (int i = 0; i < 8; i++) {
                vals[i] = __expf(vals[i] - mx);
                sum += vals[i];
            }
            #pragma unroll
            for (int o = 16; o > 0; o >>= 1)
                sum += __shfl_xor_sync(0xffffffffu, sum, o);
            const float inv = 1.f / sum;
            float* arow = attn_out + (size_t)((bh * NN) + q0 + qq) * NN;
            #pragma unroll
            for (int i = 0; i < 8; i++) {
                float p = vals[i] * inv;
                Ssm[qq][lane + 32 * i] = p;
                arow[lane + 32 * i]    = p;
            }
        }
    }
    __syncthreads();

    // ---- phase 3: output = P @ V ; thread owns (d, 4 q-rows) ----
    // k unrolled by 4: uniform LDS.128 probs (pre-packed pairs) + packed FMAs.
    {
        const int d = t & 63, gg = t >> 6;      // gg in 0..3
        unsigned long long acc0 = 0ull, acc1 = 0ull, acc2 = 0ull, acc3 = 0ull;
        const float* vb = v + (size_t)bh * NN * DVD + d;
        #pragma unroll 4
        for (int k = 0; k < NN; k += 4) {
            const float v0 = vb[(size_t)(k    ) * DVD];
            const float v1 = vb[(size_t)(k + 1) * DVD];
            const float v2 = vb[(size_t)(k + 2) * DVD];
            const float v3 = vb[(size_t)(k + 3) * DVD];
            const unsigned long long vp01 = pack2(v0, v1);
            const unsigned long long vp23 = pack2(v2, v3);
            const ulonglong2 p0 = *(const ulonglong2*)&Ssm[gg     ][k];
            const ulonglong2 p1 = *(const ulonglong2*)&Ssm[gg +  4][k];
            const ulonglong2 p2 = *(const ulonglong2*)&Ssm[gg +  8][k];
            const ulonglong2 p3 = *(const ulonglong2*)&Ssm[gg + 12][k];
            acc0 = ffma2(p0.x, vp01, acc0); acc0 = ffma2(p0.y, vp23, acc0);
            acc1 = ffma2(p1.x, vp01, acc1); acc1 = ffma2(p1.y, vp23, acc1);
            acc2 = ffma2(p2.x, vp01, acc2); acc2 = ffma2(p2.y, vp23, acc2);
            acc3 = ffma2(p3.x, vp01, acc3); acc3 = ffma2(p3.y, vp23, acc3);
        }
        float* ob = out + (size_t)((bh * NN) + q0) * DVD + d;
        ob[(size_t)(gg     ) * DVD] = hadd2(acc0);
        ob[(size_t)(gg +  4) * DVD] = hadd2(acc1);
        ob[(size_t)(gg +  8) * DVD] = hadd2(acc2);
        ob[(size_t)(gg + 12) * DVD] = hadd2(acc3);
    }
}

extern "C" void kernel_launch(void* const* d_in, const int* in_sizes, int n_in,
                              void* d_out, int out_size)
{
    const float* q    = (const float*)d_in[0];
    const float* nk   = (const float*)d_in[1];
    const float* ek   = (const float*)d_in[2];
    const float* v    = (const float*)d_in[3];
    const int*   mask = (const int*)d_in[4];

    float* out      = (float*)d_out;                       // [4,8,256,64]
    float* attn_out = out + (size_t)BB * HH * NN * DVD;    // [4,8,256,256]

    sdpea_kernel<<<BB * HH * (NN / TQ), 256>>>(q, nk, ek, v, mask,
                                               out, attn_out);
}

// round 16
// speedup vs baseline: 1.4495x; 1.1368x over previous
#include <cuda_runtime.h>
#include <cuda_bf16.h>

// Problem constants (fixed by the dataset)
#define BB   4
#define HH   8
#define NN   256
#define DVD  64
#define NKD  64
#define EKD  16
#define QD   80      // NK_DIM + EK_DIM
#define TQ   16      // queries per block
#define KC   64      // keys per chunk

// dynamic smem layout (float offsets)
#define QSM_OFF 0                     // [16][80]   = 1280
#define SSM_OFF 1280                  // [16][256]  = 4096
#define NKS_OFF (1280 + 4096)         // [64][64] swizzled = 4096
#define PS_OFF  (1280 + 4096 + 4096)  // [16][256] edge partials = 4096
#define SMEM_FLOATS (1280 + 4096 + 4096 + 4096)
#define SMEM_BYTES  (SMEM_FLOATS * 4) // 54272

// ---- packed fp32x2 helpers (ptxas never emits these from C++) ----
__device__ __forceinline__ unsigned long long ffma2(unsigned long long a,
                                                    unsigned long long b,
                                                    unsigned long long c) {
    unsigned long long d;
    asm("fma.rn.f32x2 %0, %1, %2, %3;" : "=l"(d) : "l"(a), "l"(b), "l"(c));
    return d;
}
__device__ __forceinline__ unsigned long long add2(unsigned long long a,
                                                   unsigned long long b) {
    unsigned long long d;
    asm("add.rn.f32x2 %0, %1, %2;" : "=l"(d) : "l"(a), "l"(b));
    return d;
}
__device__ __forceinline__ unsigned long long pack2(float lo, float hi) {
    unsigned long long r;
    asm("mov.b64 %0, {%1, %2};" : "=l"(r) : "f"(lo), "f"(hi));
    return r;
}
__device__ __forceinline__ float hadd2(unsigned long long a) {
    float lo, hi;
    asm("mov.b64 {%0, %1}, %2;" : "=f"(lo), "=f"(hi) : "l"(a));
    return lo + hi;
}

// ============================================================
// Fused kernel. Per key-chunk of 64:
//   stage nk (coalesced, XOR-swizzled smem) +
//   edge pass: lane=(key-octet,seg) -> 4-wf contiguous LDG.128,
//              per-lane 4-float partial dot -> ps (STS.32, 1wf)
//   node pass: thread=(kl,g) sums node dot (FFMA2) + 4 edge
//              partials via one LDS.128 + packed add.
// Then softmax + P@V as before.
// grid = 512 blocks, 256 threads, 4 CTAs/SM (53 KB dyn smem).
// ============================================================
__global__ __launch_bounds__(256, 4)
void sdpea_kernel(const float* __restrict__ qg,
                  const float* __restrict__ nk,
                  const float* __restrict__ ek,
                  const float* __restrict__ v,
                  const int*   __restrict__ mask,
                  float* __restrict__ out,       // [B,H,N,DV]
                  float* __restrict__ attn_out)  // [B,H,N,N]
{
    extern __shared__ __align__(16) float sm[];
    float (*qsm)[QD] = (float (*)[QD])(sm + QSM_OFF);
    float (*Ssm)[NN] = (float (*)[NN])(sm + SSM_OFF);
    float*  nks      = sm + NKS_OFF;                 // [64][64], XOR swizzle
    float (*ps)[NN]  = (float (*)[NN])(sm + PS_OFF); // [q][kloc*4+seg]

    const int bx = blockIdx.x;
    const int bh = bx >> 4;          // 0..31  (b*H + h)
    const int qt = bx & 15;          // 0..15
    const int b  = bh >> 3;
    const int q0 = qt * TQ;
    const int t  = threadIdx.x;      // 0..255

    // ---- load q tile (16 x 80 floats) ----
    for (int i = t; i < TQ * QD; i += 256) {
        int qq = i / QD, d = i % QD;
        qsm[qq][d] = qg[(size_t)((bh * NN) + q0 + qq) * QD + d];
    }

    const int kl = t & 63;           // node-pass key lane
    const int g  = t >> 6;           // node-pass q group
    const int*   mb  = mask + (size_t)b * NN * NN;
    const float* ekb = ek + (size_t)bh * NN * NN * EKD;   // [q][k][16]

    const int w    = t >> 5;         // edge-pass warp
    const int lane = t & 31;
    const int kk   = lane >> 2;      // key within octet
    const int seg  = lane & 3;       // 16B segment of ek row
    const int swz  = kl & 15;        // XOR swizzle key for node reads

    for (int c = 0; c < 4; c++) {
        const int kbase = c * KC;
        __syncthreads();   // previous chunk's nks/ps consumers done

        // ---- stage nk chunk: coalesced LDG.128 -> swizzled STS.128 ----
        {
            const float4* src = (const float4*)(nk + (size_t)(bh * NN + kbase) * NKD);
            #pragma unroll
            for (int it = 0; it < 4; it++) {
                const int idx  = t + it * 256;       // 0..1023
                const int row  = idx >> 4;
                const int col4 = idx & 15;
                const float4 vv = src[(size_t)row * 16 + col4];
                *(float4*)&nks[row * 64 + ((col4 ^ (row & 15)) * 4)] = vv;
            }
        }

        // ---- edge partials: warp w covers queries {2w, 2w+1} ----
        // Each LDG.128 is 512B-contiguous across the warp (4 wf).
        #pragma unroll
        for (int qq = 0; qq < 2; qq++) {
            const int ql = 2 * w + qq;
            const ulonglong2 qe = *(const ulonglong2*)&qsm[ql][NKD + seg * 4];
            const float* ebase =
                ekb + ((size_t)(q0 + ql) * NN + kbase + kk) * EKD + seg * 4;
            #pragma unroll
            for (int m = 0; m < 8; m++) {
                const ulonglong2 e = *(const ulonglong2*)(ebase + m * 8 * EKD);
                unsigned long long a = ffma2(e.x, qe.x, 0ull);
                a = ffma2(e.y, qe.y, a);
                ps[ql][(m * 8 + kk) * 4 + seg] = hadd2(a);
            }
        }
        __syncthreads();

        // ---- node pass: thread=(kl,g), queries {g,g+4,g+8,g+12} ----
        const int k = kbase + kl;

        int m4[4];
        #pragma unroll
        for (int j = 0; j < 4; j++)
            m4[j] = mb[(q0 + g + 4 * j) * NN + k];

        // edge partials: one LDS.128 per query, fold pairwise (packed add)
        unsigned long long a0, a1, a2, a3;
        {
            const ulonglong2 p0 = *(const ulonglong2*)&ps[g     ][kl * 4];
            const ulonglong2 p1 = *(const ulonglong2*)&ps[g +  4][kl * 4];
            const ulonglong2 p2 = *(const ulonglong2*)&ps[g +  8][kl * 4];
            const ulonglong2 p3 = *(const ulonglong2*)&ps[g + 12][kl * 4];
            a0 = add2(p0.x, p0.y);
            a1 = add2(p1.x, p1.y);
            a2 = add2(p2.x, p2.y);
            a3 = add2(p3.x, p3.y);
        }

        #pragma unroll
        for (int i = 0; i < 16; i++) {
            // physical slot (i^swz) holds LOGICAL column i for row kl
            const ulonglong2 nv =
                *(const ulonglong2*)&nks[kl * 64 + ((i ^ swz) * 4)];
            const int col = 4 * i;               // logical column (bugfix)
            const ulonglong2 q0v = *(const ulonglong2*)&qsm[g     ][col];
            const ulonglong2 q1v = *(const ulonglong2*)&qsm[g +  4][col];
            const ulonglong2 q2v = *(const ulonglong2*)&qsm[g +  8][col];
            const ulonglong2 q3v = *(const ulonglong2*)&qsm[g + 12][col];
            a0 = ffma2(nv.x, q0v.x, a0); a0 = ffma2(nv.y, q0v.y, a0);
            a1 = ffma2(nv.x, q1v.x, a1); a1 = ffma2(nv.y, q1v.y, a1);
            a2 = ffma2(nv.x, q2v.x, a2); a2 = ffma2(nv.y, q2v.y, a2);
            a3 = ffma2(nv.x, q3v.x, a3); a3 = ffma2(nv.y, q3v.y, a3);
        }

        float sv;
        sv = hadd2(a0) * 0.125f; if (m4[0] == 0) sv = -1000000000.0f; Ssm[g     ][k] = sv;
        sv = hadd2(a1) * 0.125f; if (m4[1] == 0) sv = -1000000000.0f; Ssm[g +  4][k] = sv;
        sv = hadd2(a2) * 0.125f; if (m4[2] == 0) sv = -1000000000.0f; Ssm[g +  8][k] = sv;
        sv = hadd2(a3) * 0.125f; if (m4[3] == 0) sv = -1000000000.0f; Ssm[g + 12][k] = sv;
    }
    __syncthreads();

    // ---- phase 2: softmax, one warp per row (8 warps, 16 rows) ----
    {
        for (int qq = w; qq < TQ; qq += 8) {
            float vals[8];
            float mx = -3.4e38f;
            #pragma unroll
            for (int i = 0; i < 8; i++) {
                vals[i] = Ssm[qq][lane + 32 * i];
                mx = fmaxf(mx, vals[i]);
            }
            #pragma unroll
            for (int o = 16; o > 0; o >>= 1)
                mx = fmaxf(mx, __shfl_xor_sync(0xffffffffu, mx, o));
            float sum = 0.f;
            #pragma unroll
            for (int i = 0; i < 8; i++) {
                vals[i] = __expf(vals[i] - mx);
                sum += vals[i];
            }
            #pragma unroll
            for (int o = 16; o > 0; o >>= 1)
                sum += __shfl_xor_sync(0xffffffffu, sum, o);
            const float inv = 1.f / sum;
            float* arow = attn_out + (size_t)((bh * NN) + q0 + qq) * NN;
            #pragma unroll
            for (int i = 0; i < 8; i++) {
                float p = vals[i] * inv;
                Ssm[qq][lane + 32 * i] = p;
                arow[lane + 32 * i]    = p;
            }
        }
    }
    __syncthreads();

    // ---- phase 3: output = P @ V ; thread owns (d, 4 q-rows) ----
    {
        const int d = t & 63, gg = t >> 6;
        unsigned long long acc0 = 0ull, acc1 = 0ull, acc2 = 0ull, acc3 = 0ull;
        const float* vb = v + (size_t)bh * NN * DVD + d;
        #pragma unroll 4
        for (int k = 0; k < NN; k += 4) {
            const float v0 = vb[(size_t)(k    ) * DVD];
            const float v1 = vb[(size_t)(k + 1) * DVD];
            const float v2 = vb[(size_t)(k + 2) * DVD];
            const float v3 = vb[(size_t)(k + 3) * DVD];
            const unsigned long long vp01 = pack2(v0, v1);
            const unsigned long long vp23 = pack2(v2, v3);
            const ulonglong2 p0 = *(const ulonglong2*)&Ssm[gg     ][k];
            const ulonglong2 p1 = *(const ulonglong2*)&Ssm[gg +  4][k];
            const ulonglong2 p2 = *(const ulonglong2*)&Ssm[gg +  8][k];
            const ulonglong2 p3 = *(const ulonglong2*)&Ssm[gg + 12][k];
            acc0 = ffma2(p0.x, vp01, acc0); acc0 = ffma2(p0.y, vp23, acc0);
            acc1 = ffma2(p1.x, vp01, acc1); acc1 = ffma2(p1.y, vp23, acc1);
            acc2 = ffma2(p2.x, vp01, acc2); acc2 = ffma2(p2.y, vp23, acc2);
            acc3 = ffma2(p3.x, vp01, acc3); acc3 = ffma2(p3.y, vp23, acc3);
        }
        float* ob = out + (size_t)((bh * NN) + q0) * DVD + d;
        ob[(size_t)(gg     ) * DVD] = hadd2(acc0);
        ob[(size_t)(gg +  4) * DVD] = hadd2(acc1);
        ob[(size_t)(gg +  8) * DVD] = hadd2(acc2);
        ob[(size_t)(gg + 12) * DVD] = hadd2(acc3);
    }
}

extern "C" void kernel_launch(void* const* d_in, const int* in_sizes, int n_in,
                              void* d_out, int out_size)
{
    const float* q    = (const float*)d_in[0];
    const float* nk   = (const float*)d_in[1];
    const float* ek   = (const float*)d_in[2];
    const float* v    = (const float*)d_in[3];
    const int*   mask = (const int*)d_in[4];

    float* out      = (float*)d_out;                       // [4,8,256,64]
    float* attn_out = out + (size_t)BB * HH * NN * DVD;    // [4,8,256,256]

    // opt-in to >48KB dynamic smem (idempotent; not a stream op)
    cudaFuncSetAttribute(sdpea_kernel,
                         cudaFuncAttributeMaxDynamicSharedMemorySize,
                         SMEM_BYTES);

    sdpea_kernel<<<BB * HH * (NN / TQ), 256, SMEM_BYTES>>>(q, nk, ek, v, mask,
                                                           out, attn_out);
}

// round 17
// speedup vs baseline: 1.5878x; 1.0954x over previous
#include <cuda_runtime.h>
#include <cuda_bf16.h>

// Problem constants (fixed by the dataset)
#define BB   4
#define HH   8
#define NN   256
#define DVD  64
#define NKD  64
#define EKD  16
#define QD   80      // NK_DIM + EK_DIM
#define TQ   16      // queries per block
#define KC   64      // keys per chunk

// ---- packed fp32x2 helpers (ptxas never emits these from C++) ----
__device__ __forceinline__ unsigned long long ffma2(unsigned long long a,
                                                    unsigned long long b,
                                                    unsigned long long c) {
    unsigned long long d;
    asm("fma.rn.f32x2 %0, %1, %2, %3;" : "=l"(d) : "l"(a), "l"(b), "l"(c));
    return d;
}
__device__ __forceinline__ unsigned long long pack2(float lo, float hi) {
    unsigned long long r;
    asm("mov.b64 %0, {%1, %2};" : "=l"(r) : "f"(lo), "f"(hi));
    return r;
}
__device__ __forceinline__ float hadd2(unsigned long long a) {
    float lo, hi;
    asm("mov.b64 {%0, %1}, %2;" : "=f"(lo), "=f"(hi) : "l"(a));
    return lo + hi;
}

// ============================================================
// Fused kernel. Per key-chunk of 64:
//   stage nk (coalesced, XOR-swizzled smem)
//   edge pass: lane=(key-octet,seg) -> 4-wf contiguous LDG.128,
//              4-dim partial; ONE shfl_xor(1) folds seg pairs;
//              2 floats per (q,k) stored to ps2 (8 KB).
//   node pass: thread=(kl,g); acc f32x2 INITIALIZED from the
//              ps2 pair (one LDS.64), then node FFMA2 dots.
// Then softmax + P@V.
// grid = 512 blocks, 256 threads, 5 CTAs/SM (45 KB smem, <=51 regs).
// ============================================================
__global__ __launch_bounds__(256, 5)
void sdpea_kernel(const float* __restrict__ qg,
                  const float* __restrict__ nk,
                  const float* __restrict__ ek,
                  const float* __restrict__ v,
                  const int*   __restrict__ mask,
                  float* __restrict__ out,       // [B,H,N,DV]
                  float* __restrict__ attn_out)  // [B,H,N,N]
{
    __shared__ __align__(16) float qsm[TQ][QD];     // q tile (qn||qe)
    __shared__ __align__(16) float Ssm[TQ][NN];     // scores -> probs
    __shared__ __align__(16) float nks[KC * 64];    // nk chunk, XOR swizzle
    __shared__ __align__(16) float ps2[TQ][2 * KC]; // edge partial pairs

    const int bx = blockIdx.x;
    const int bh = bx >> 4;          // 0..31  (b*H + h)
    const int qt = bx & 15;          // 0..15
    const int b  = bh >> 3;
    const int q0 = qt * TQ;
    const int t  = threadIdx.x;      // 0..255

    // ---- load q tile (16 x 80 floats) ----
    for (int i = t; i < TQ * QD; i += 256) {
        int qq = i / QD, d = i % QD;
        qsm[qq][d] = qg[(size_t)((bh * NN) + q0 + qq) * QD + d];
    }

    const int kl = t & 63;           // node-pass key lane
    const int g  = t >> 6;           // node-pass q group
    const int*   mb  = mask + (size_t)b * NN * NN;
    const float* ekb = ek + (size_t)bh * NN * NN * EKD;   // [q][k][16]

    const int w    = t >> 5;         // edge-pass warp
    const int lane = t & 31;
    const int kk   = lane >> 2;      // key within octet
    const int seg  = lane & 3;       // 16B segment of ek row
    const int swz  = kl & 15;        // XOR swizzle key for node reads

    for (int c = 0; c < 4; c++) {
        const int kbase = c * KC;
        __syncthreads();   // previous chunk's nks/ps2 consumers done

        // ---- stage nk chunk: coalesced LDG.128 -> swizzled STS.128 ----
        {
            const float4* src = (const float4*)(nk + (size_t)(bh * NN + kbase) * NKD);
            #pragma unroll
            for (int it = 0; it < 4; it++) {
                const int idx  = t + it * 256;       // 0..1023
                const int row  = idx >> 4;
                const int col4 = idx & 15;
                const float4 vv = src[(size_t)row * 16 + col4];
                *(float4*)&nks[row * 64 + ((col4 ^ (row & 15)) * 4)] = vv;
            }
        }

        // ---- edge partials: warp w covers queries {2w, 2w+1} ----
        // Each LDG.128 is 512B-contiguous across the warp (4 wf).
        #pragma unroll
        for (int qq = 0; qq < 2; qq++) {
            const int ql = 2 * w + qq;
            const ulonglong2 qe = *(const ulonglong2*)&qsm[ql][NKD + seg * 4];
            const float* ebase =
                ekb + ((size_t)(q0 + ql) * NN + kbase + kk) * EKD + seg * 4;
            #pragma unroll
            for (int m = 0; m < 8; m++) {
                const ulonglong2 e = *(const ulonglong2*)(ebase + m * 8 * EKD);
                unsigned long long a = ffma2(e.x, qe.x, 0ull);
                a = ffma2(e.y, qe.y, a);
                float p = hadd2(a);
                // fold seg pairs (0+1, 2+3) with one shfl
                p += __shfl_xor_sync(0xffffffffu, p, 1);
                if ((seg & 1) == 0)
                    ps2[ql][(m * 8 + kk) * 2 + (seg >> 1)] = p;
            }
        }
        __syncthreads();

        // ---- node pass: thread=(kl,g), queries {g,g+4,g+8,g+12} ----
        const int k = kbase + kl;

        int m4[4];
        #pragma unroll
        for (int j = 0; j < 4; j++)
            m4[j] = mb[(q0 + g + 4 * j) * NN + k];

        // acc init = edge partial pair (f32x2); halves summed at the end
        unsigned long long a0 = *(const unsigned long long*)&ps2[g     ][kl * 2];
        unsigned long long a1 = *(const unsigned long long*)&ps2[g +  4][kl * 2];
        unsigned long long a2 = *(const unsigned long long*)&ps2[g +  8][kl * 2];
        unsigned long long a3 = *(const unsigned long long*)&ps2[g + 12][kl * 2];

        #pragma unroll
        for (int i = 0; i < 16; i++) {
            // physical slot (i^swz) holds LOGICAL column i for row kl
            const ulonglong2 nv =
                *(const ulonglong2*)&nks[kl * 64 + ((i ^ swz) * 4)];
            const int col = 4 * i;               // logical column
            const ulonglong2 q0v = *(const ulonglong2*)&qsm[g     ][col];
            const ulonglong2 q1v = *(const ulonglong2*)&qsm[g +  4][col];
            const ulonglong2 q2v = *(const ulonglong2*)&qsm[g +  8][col];
            const ulonglong2 q3v = *(const ulonglong2*)&qsm[g + 12][col];
            a0 = ffma2(nv.x, q0v.x, a0); a0 = ffma2(nv.y, q0v.y, a0);
            a1 = ffma2(nv.x, q1v.x, a1); a1 = ffma2(nv.y, q1v.y, a1);
            a2 = ffma2(nv.x, q2v.x, a2); a2 = ffma2(nv.y, q2v.y, a2);
            a3 = ffma2(nv.x, q3v.x, a3); a3 = ffma2(nv.y, q3v.y, a3);
        }

        float sv;
        sv = hadd2(a0) * 0.125f; if (m4[0] == 0) sv = -1000000000.0f; Ssm[g     ][k] = sv;
        sv = hadd2(a1) * 0.125f; if (m4[1] == 0) sv = -1000000000.0f; Ssm[g +  4][k] = sv;
        sv = hadd2(a2) * 0.125f; if (m4[2] == 0) sv = -1000000000.0f; Ssm[g +  8][k] = sv;
        sv = hadd2(a3) * 0.125f; if (m4[3] == 0) sv = -1000000000.0f; Ssm[g + 12][k] = sv;
    }
    __syncthreads();

    // ---- phase 2: softmax, one warp per row (8 warps, 16 rows) ----
    {
        for (int qq = w; qq < TQ; qq += 8) {
            float vals[8];
            float mx = -3.4e38f;
            #pragma unroll
            for (int i = 0; i < 8; i++) {
                vals[i] = Ssm[qq][lane + 32 * i];
                mx = fmaxf(mx, vals[i]);
            }
            #pragma unroll
            for (int o = 16; o > 0; o >>= 1)
                mx = fmaxf(mx, __shfl_xor_sync(0xffffffffu, mx, o));
            float sum = 0.f;
            #pragma unroll
            for (int i = 0; i < 8; i++) {
                vals[i] = __expf(vals[i] - mx);
                sum += vals[i];
            }
            #pragma unroll
            for (int o = 16; o > 0; o >>= 1)
                sum += __shfl_xor_sync(0xffffffffu, sum, o);
            const float inv = 1.f / sum;
            float* arow = attn_out + (size_t)((bh * NN) + q0 + qq) * NN;
            #pragma unroll
            for (int i = 0; i < 8; i++) {
                float p = vals[i] * inv;
                Ssm[qq][lane + 32 * i] = p;
                arow[lane + 32 * i]    = p;
            }
        }
    }
    __syncthreads();

    // ---- phase 3: output = P @ V ; thread owns (d, 4 q-rows) ----
    {
        const int d = t & 63, gg = t >> 6;
        unsigned long long acc0 = 0ull, acc1 = 0ull, acc2 = 0ull, acc3 = 0ull;
        const float* vb = v + (size_t)bh * NN * DVD + d;
        #pragma unroll 4
        for (int k = 0; k < NN; k += 4) {
            const float v0 = vb[(size_t)(k    ) * DVD];
            const float v1 = vb[(size_t)(k + 1) * DVD];
            const float v2 = vb[(size_t)(k + 2) * DVD];
            const float v3 = vb[(size_t)(k + 3) * DVD];
            const unsigned long long vp01 = pack2(v0, v1);
            const unsigned long long vp23 = pack2(v2, v3);
            const ulonglong2 p0 = *(const ulonglong2*)&Ssm[gg     ][k];
            const ulonglong2 p1 = *(const ulonglong2*)&Ssm[gg +  4][k];
            const ulonglong2 p2 = *(const ulonglong2*)&Ssm[gg +  8][k];
            const ulonglong2 p3 = *(const ulonglong2*)&Ssm[gg + 12][k];
            acc0 = ffma2(p0.x, vp01, acc0); acc0 = ffma2(p0.y, vp23, acc0);
            acc1 = ffma2(p1.x, vp01, acc1); acc1 = ffma2(p1.y, vp23, acc1);
            acc2 = ffma2(p2.x, vp01, acc2); acc2 = ffma2(p2.y, vp23, acc2);
            acc3 = ffma2(p3.x, vp01, acc3); acc3 = ffma2(p3.y, vp23, acc3);
        }
        float* ob = out + (size_t)((bh * NN) + q0) * DVD + d;
        ob[(size_t)(gg     ) * DVD] = hadd2(acc0);
        ob[(size_t)(gg +  4) * DVD] = hadd2(acc1);
        ob[(size_t)(gg +  8) * DVD] = hadd2(acc2);
        ob[(size_t)(gg + 12) * DVD] = hadd2(acc3);
    }
}

extern "C" void kernel_launch(void* const* d_in, const int* in_sizes, int n_in,
                              void* d_out, int out_size)
{
    const float* q    = (const float*)d_in[0];
    const float* nk   = (const float*)d_in[1];
    const float* ek   = (const float*)d_in[2];
    const float* v    = (const float*)d_in[3];
    const int*   mask = (const int*)d_in[4];

    float* out      = (float*)d_out;                       // [4,8,256,64]
    float* attn_out = out + (size_t)BB * HH * NN * DVD;    // [4,8,256,256]

    sdpea_kernel<<<BB * HH * (NN / TQ), 256>>>(q, nk, ek, v, mask,
                                               out, attn_out);
}